// round 9
// baseline (speedup 1.0000x reference)
#include <cuda_runtime.h>
#include <math.h>

// Problem constants
#define BB    64
#define CC    512
#define NN    1024          // 32*32 spatial
#define OO    25            // 1 conf + 20 cls + 4 box
#define OPAD  28            // pad rows to multiple of 4 for ulonglong2 smem loads
#define NCLS  20
#define CONF_T 0.01f
#define NMS_T  0.5f
#define EPS_IOU 1e-28f
#define INV_SCALE 0.0009765625f   // 1/1024
#define MAXC  128           // per-(image,class) candidate cap; mean ~51, ~11 sigma
#define FULLM 0xffffffffu
#define PF    8             // feat prefetch depth (covers ~577cyc DRAM latency)

typedef unsigned long long u64;

// Compacted per-(image,class) candidate records, filled by GEMM epilogue.
// g_cnt zeroed at module load and re-zeroed by k_nms each launch -> replay-safe.
__device__ int    g_cnt [BB*NCLS];
__device__ float4 g_cbox[BB*NCLS*MAXC];   // offset boxes
__device__ u64    g_ckey[BB*NCLS*MAXC];   // (score desc, pixel asc) sort key

__device__ __forceinline__ float sigm(float x) { return 1.0f / (1.0f + expf(-x)); }

// packed f32x2 fma, lane-wise round-to-nearest (bitwise == scalar fmaf per lane)
#define FMA2(c, a, b) asm("fma.rn.f32x2 %0, %1, %2, %3;" : "=l"(c) : "l"(a), "l"(b), "l"(c))

__device__ __forceinline__ u64 pack2(float x) {
    u64 r; unsigned xb = __float_as_uint(x);
    asm("mov.b64 %0, {%1, %1};" : "=l"(r) : "r"(xb));
    return r;
}
__device__ __forceinline__ void unpack2(u64 v, float& lo, float& hi) {
    unsigned l, h;
    asm("mov.b64 {%0, %1}, %2;" : "=r"(l), "=r"(h) : "l"(v));
    lo = __uint_as_float(l); hi = __uint_as_float(h);
}

// Decode one pixel given its 25 raw logits (bias added here).
__device__ __forceinline__ void decode_write(int b, int n, const float* acc,
                                             const float* b_s, float* __restrict__ out)
{
    float p[OO];
    #pragma unroll
    for (int o = 0; o < OO; o++) p[o] = acc[o] + b_s[o];

    float conf = sigm(p[0]);

    // argmax over raw class logits (== argmax of softmax), first-max tie-break
    float m = p[1]; int am = 0;
    #pragma unroll
    for (int k = 1; k < NCLS; k++)
        if (p[1 + k] > m) { m = p[1 + k]; am = k; }

    float s = 0.0f;
    #pragma unroll
    for (int k = 0; k < NCLS; k++) s += expf(p[1 + k] - m);
    float score = conf / s;          // conf * max(softmax) == conf / sum(exp(l-m))

    float gx = (float)(n & 31), gy = (float)(n >> 5);
    float cx = (sigm(p[21]) + gx) * 32.0f;
    float cy = (sigm(p[22]) + gy) * 32.0f;
    float w  = expf(p[23]);
    float h  = expf(p[24]);
    float hw = __fmul_rn(w, 0.5f);
    float hh = __fmul_rn(h, 0.5f);
    float x1 = fminf(fmaxf(__fmul_rn(cx - hw, INV_SCALE), 0.0f), 1.0f);
    float y1 = fminf(fmaxf(__fmul_rn(cy - hh, INV_SCALE), 0.0f), 1.0f);
    float x2 = fminf(fmaxf(__fmul_rn(cx + hw, INV_SCALE), 0.0f), 1.0f);
    float y2 = fminf(fmaxf(__fmul_rn(cy + hh, INV_SCALE), 0.0f), 1.0f);

    int i = b * NN + n;
    ((float4*)out)[i] = make_float4(x1, y1, x2, y2);     // boxes region [0, B*N*4)
    out[BB*NN*4 + i] = score;                            // scores
    out[BB*NN*5 + i] = (float)am;                        // cls_inds (as float)
    out[BB*NN*6 + i] = 0.0f;                             // keep default (NMS sets 1s)

    // Append compact record. Arrival order irrelevant: NMS sorts by the u64 key
    // (score desc, pixel asc), so results are deterministic.
    if (score > CONF_T) {
        int idx  = b * NCLS + am;
        int slot = atomicAdd(&g_cnt[idx], 1);
        if (slot < MAXC) {
            float off = __fmul_rn(2.0f, (float)am);
            g_cbox[idx * MAXC + slot] =
                make_float4(x1 + off, y1 + off, x2 + off, y2 + off);
            g_ckey[idx * MAXC + slot] =
                ((u64)__float_as_uint(score) << 32) | (u64)(NN - 1 - n);
        }
    }
}

#define WSMEM_WORDS (CC * OPAD)                 // 14336 words = 56 KB
#define SMEM_BYTES  ((WSMEM_WORDS + 32) * 4)

// Fused GEMM (65536 x 512 x 25) + decode. 512 blocks x 128 threads, 1 px/thread.
// 57KB smem -> 3 blocks/SM co-resident = 12 warps/SM (3/SMSP) for latency hiding.
// All 512 weight rows staged once; feat via explicit 8-deep prefetch pipeline.
__global__ __launch_bounds__(128)
void k_gemm_decode(const float* __restrict__ feat,
                   const float* __restrict__ w_pred,
                   const float* __restrict__ b_pred,
                   float* __restrict__ out)
{
    extern __shared__ float smem_dyn[];
    float* w_s = smem_dyn;                      // CC x OPAD
    float* b_s = smem_dyn + WSMEM_WORDS;        // OO

    const int tid = threadIdx.x;
    const int b   = blockIdx.x >> 3;
    const int n0  = ((blockIdx.x & 7) << 7) | tid;
    const float* fp = feat + (size_t)b * CC * NN + n0;

    // Stage all weights (padded rows -> ulonglong2-aligned channel pairs)
    for (int i = tid; i < WSMEM_WORDS; i += 128) {
        int c = i / OPAD, o = i - c * OPAD;
        w_s[i] = (o < OO) ? w_pred[o * CC + c] : 0.0f;
    }
    if (tid < OO) b_s[tid] = b_pred[tid];
    __syncthreads();

    u64 acc[13];                                // channel pairs {2q,2q+1}
    #pragma unroll
    for (int q = 0; q < 13; q++) acc[q] = 0ull;

    float buf[PF];
    #pragma unroll
    for (int k = 0; k < PF; k++) buf[k] = __ldg(fp + (size_t)k * NN);

    #pragma unroll 1
    for (int cc = 0; cc < CC - PF; cc += PF) {
        float cur[PF];
        #pragma unroll
        for (int k = 0; k < PF; k++) cur[k] = buf[k];
        #pragma unroll
        for (int k = 0; k < PF; k++)
            buf[k] = __ldg(fp + (size_t)(cc + PF + k) * NN);
        #pragma unroll
        for (int k = 0; k < PF; k++) {
            u64 fA = pack2(cur[k]);
            const ulonglong2* wr = (const ulonglong2*)(w_s + (cc + k) * OPAD);
            #pragma unroll
            for (int j = 0; j < 7; j++) {
                ulonglong2 q = wr[j];           // one LDS.128 -> two channel pairs
                FMA2(acc[2*j], fA, q.x);
                if (2*j + 1 < 13) FMA2(acc[2*j + 1], fA, q.y);
            }
        }
    }
    #pragma unroll
    for (int k = 0; k < PF; k++) {              // epilogue: last PF channels
        u64 fA = pack2(buf[k]);
        const ulonglong2* wr = (const ulonglong2*)(w_s + (CC - PF + k) * OPAD);
        #pragma unroll
        for (int j = 0; j < 7; j++) {
            ulonglong2 q = wr[j];
            FMA2(acc[2*j], fA, q.x);
            if (2*j + 1 < 13) FMA2(acc[2*j + 1], fA, q.y);
        }
    }

    float acc0[26];
    #pragma unroll
    for (int q = 0; q < 13; q++) unpack2(acc[q], acc0[2*q], acc0[2*q + 1]);
    decode_write(b, n0, acc0, b_s, out);
}

// NMS: one 64-thread block per (image, class). Class offset 2.0 makes cross-class
// IoU ~0 => per-class greedy == the reference's global sorted loop exactly.
// Sub-threshold boxes can neither suppress nor be kept -> excluded at gather.
// Matrix build: thread-per-row, all threads sweep j together (sbox[j] = broadcast
// LDS, rows live in registers, no ballots/atomics). Then a trivial serial walk.
__global__ __launch_bounds__(64)
void k_nms(float* __restrict__ out)
{
    const int b    = blockIdx.x;
    const int c    = blockIdx.y;
    const int idx  = b * NCLS + c;
    const int tid  = threadIdx.x;

    __shared__ int    s_cnt;
    __shared__ u64    tkey[MAXC];
    __shared__ float4 tbox[MAXC];
    __shared__ float4 sbox[MAXC];    // rank-sorted boxes
    __shared__ float  sarea[MAXC];
    __shared__ short  ssn[MAXC];     // rank-sorted pixel index
    __shared__ uint4  rows[MAXC];    // suppression bit-matrix rows

    if (tid == 0) { int ct = g_cnt[idx]; g_cnt[idx] = 0; s_cnt = min(ct, MAXC); }
    __syncthreads();
    const int cnt = s_cnt;
    if (cnt == 0) return;

    for (int i = tid; i < cnt; i += 64) {
        tkey[i] = g_ckey[idx * MAXC + i];       // coalesced
        tbox[i] = g_cbox[idx * MAXC + i];
    }
    __syncthreads();

    // Rank sort (keys distinct -> permutation), == jnp.argsort(-scores) stability.
    for (int i = tid; i < cnt; i += 64) {
        u64 ki = tkey[i];
        int rank = 0;
        for (int j = 0; j < cnt; j++) rank += (tkey[j] > ki);
        float4 bx = tbox[i];
        sbox[rank]  = bx;
        sarea[rank] = __fmul_rn(bx.z - bx.x, bx.w - bx.y);
        ssn[rank]   = (short)(NN - 1 - (int)(ki & 0xffffffffu));
    }
    __syncthreads();

    // Suppression matrix: thread t owns rows t and t+64; sweep j uniformly.
    #pragma unroll 1
    for (int rbase = 0; rbase < cnt; rbase += 64) {
        int i = rbase + tid;
        float4 kb; float ka = 0.0f;
        bool live = (i < cnt);
        if (live) { kb = sbox[i]; ka = sarea[i]; }
        unsigned w0 = 0, w1 = 0, w2 = 0, w3 = 0;
        for (int j = 1; j < cnt; j++) {         // j=0 can't be suppressed by anyone
            float4 ob = sbox[j];                // broadcast
            float oa = sarea[j];                // broadcast
            if (live && j > i) {
                float xx1 = fmaxf(kb.x, ob.x);
                float yy1 = fmaxf(kb.y, ob.y);
                float xx2 = fminf(kb.z, ob.z);
                float yy2 = fminf(kb.w, ob.w);
                float w = fmaxf(EPS_IOU, xx2 - xx1);
                float h = fmaxf(EPS_IOU, yy2 - yy1);
                float inter = __fmul_rn(w, h);
                float iou = inter / (ka + oa - inter);
                if (iou > NMS_T) {
                    unsigned bit = 1u << (j & 31);
                    if      (j < 32) w0 |= bit;
                    else if (j < 64) w1 |= bit;
                    else if (j < 96) w2 |= bit;
                    else             w3 |= bit;
                }
            }
        }
        if (live) rows[i] = make_uint4(w0, w1, w2, w3);
    }
    __syncthreads();

    // Serial walk (thread 0): act mask in registers, rows[k] loads pipeline.
    if (tid == 0) {
        float* keep = out + (size_t)BB * NN * 6 + (size_t)b * NN;
        unsigned a0 = FULLM, a1 = FULLM, a2 = FULLM, a3 = FULLM;
        for (int k = 0; k < cnt; k++) {
            uint4 r = rows[k];
            unsigned aw = (k < 32) ? a0 : (k < 64) ? a1 : (k < 96) ? a2 : a3;
            if ((aw >> (k & 31)) & 1u) {
                keep[ssn[k]] = 1.0f;
                a0 &= ~r.x; a1 &= ~r.y; a2 &= ~r.z; a3 &= ~r.w;
            }
        }
    }
}

extern "C" void kernel_launch(void* const* d_in, const int* in_sizes, int n_in,
                              void* d_out, int out_size)
{
    const float* feat   = (const float*)d_in[0];
    const float* w_pred = (const float*)d_in[1];
    const float* b_pred = (const float*)d_in[2];
    float* out = (float*)d_out;

    static int smem_set = 0;
    if (!smem_set) {
        cudaFuncSetAttribute(k_gemm_decode,
                             cudaFuncAttributeMaxDynamicSharedMemorySize, SMEM_BYTES);
        smem_set = 1;
    }

    k_gemm_decode<<<512, 128, SMEM_BYTES>>>(feat, w_pred, b_pred, out);
    k_nms<<<dim3(BB, NCLS), 64>>>(out);
}

// round 10
// speedup vs baseline: 1.7569x; 1.7569x over previous
#include <cuda_runtime.h>
#include <math.h>

// Problem constants
#define BB    64
#define CC    512
#define NN    1024          // 32*32 spatial
#define OO    25            // 1 conf + 20 cls + 4 box
#define OPAD  28            // pad rows to multiple of 4 for ulonglong2 smem loads
#define NCLS  20
#define CONF_T 0.01f
#define NMS_T  0.5f
#define EPS_IOU 1e-28f
#define INV_SCALE 0.0009765625f   // 1/1024
#define MAXC  128           // per-(image,class) candidate cap; mean ~51, ~11 sigma
#define FULLM 0xffffffffu
#define PF    8             // feat prefetch depth (covers ~577cyc DRAM latency)

typedef unsigned long long u64;

// Compacted per-(image,class) candidate records, filled by GEMM epilogue.
// g_cnt zeroed at module load and re-zeroed by k_nms each launch -> replay-safe.
__device__ int    g_cnt [BB*NCLS];
__device__ float4 g_cbox[BB*NCLS*MAXC];   // offset boxes
__device__ u64    g_ckey[BB*NCLS*MAXC];   // (score desc, pixel asc) sort key

__device__ __forceinline__ float sigm(float x) { return 1.0f / (1.0f + expf(-x)); }

// packed f32x2 fma, lane-wise round-to-nearest (bitwise == scalar fmaf per lane)
#define FMA2(c, a, b) asm("fma.rn.f32x2 %0, %1, %2, %3;" : "=l"(c) : "l"(a), "l"(b), "l"(c))

__device__ __forceinline__ u64 pack2(float x) {
    u64 r; unsigned xb = __float_as_uint(x);
    asm("mov.b64 %0, {%1, %1};" : "=l"(r) : "r"(xb));
    return r;
}
__device__ __forceinline__ void unpack2(u64 v, float& lo, float& hi) {
    unsigned l, h;
    asm("mov.b64 {%0, %1}, %2;" : "=r"(l), "=r"(h) : "l"(v));
    lo = __uint_as_float(l); hi = __uint_as_float(h);
}

// Decode one pixel given its 25 raw logits (bias added here).
__device__ __forceinline__ void decode_write(int b, int n, const float* acc,
                                             const float* b_s, float* __restrict__ out)
{
    float p[OO];
    #pragma unroll
    for (int o = 0; o < OO; o++) p[o] = acc[o] + b_s[o];

    float conf = sigm(p[0]);

    // argmax over raw class logits (== argmax of softmax), first-max tie-break
    float m = p[1]; int am = 0;
    #pragma unroll
    for (int k = 1; k < NCLS; k++)
        if (p[1 + k] > m) { m = p[1 + k]; am = k; }

    float s = 0.0f;
    #pragma unroll
    for (int k = 0; k < NCLS; k++) s += expf(p[1 + k] - m);
    float score = conf / s;          // conf * max(softmax) == conf / sum(exp(l-m))

    float gx = (float)(n & 31), gy = (float)(n >> 5);
    float cx = (sigm(p[21]) + gx) * 32.0f;
    float cy = (sigm(p[22]) + gy) * 32.0f;
    float w  = expf(p[23]);
    float h  = expf(p[24]);
    float hw = __fmul_rn(w, 0.5f);
    float hh = __fmul_rn(h, 0.5f);
    float x1 = fminf(fmaxf(__fmul_rn(cx - hw, INV_SCALE), 0.0f), 1.0f);
    float y1 = fminf(fmaxf(__fmul_rn(cy - hh, INV_SCALE), 0.0f), 1.0f);
    float x2 = fminf(fmaxf(__fmul_rn(cx + hw, INV_SCALE), 0.0f), 1.0f);
    float y2 = fminf(fmaxf(__fmul_rn(cy + hh, INV_SCALE), 0.0f), 1.0f);

    int i = b * NN + n;
    ((float4*)out)[i] = make_float4(x1, y1, x2, y2);     // boxes region [0, B*N*4)
    out[BB*NN*4 + i] = score;                            // scores
    out[BB*NN*5 + i] = (float)am;                        // cls_inds (as float)
    out[BB*NN*6 + i] = 0.0f;                             // keep default (NMS sets 1s)

    // Append compact record. Arrival order irrelevant: NMS sorts by the u64 key
    // (score desc, pixel asc), so results are deterministic.
    if (score > CONF_T) {
        int idx  = b * NCLS + am;
        int slot = atomicAdd(&g_cnt[idx], 1);
        if (slot < MAXC) {
            float off = __fmul_rn(2.0f, (float)am);
            g_cbox[idx * MAXC + slot] =
                make_float4(x1 + off, y1 + off, x2 + off, y2 + off);
            g_ckey[idx * MAXC + slot] =
                ((u64)__float_as_uint(score) << 32) | (u64)(NN - 1 - n);
        }
    }
}

#define WSMEM_WORDS (CC * OPAD)                 // 14336 words = 56 KB
#define SMEM_BYTES  ((WSMEM_WORDS + 32) * 4)

// Fused GEMM (65536 x 512 x 25) + decode. 256 blocks x 128 threads, 2 px/thread
// (R8 configuration, measured-best). All 512 weight rows staged once in dynamic
// smem; feat loaded as float2 with an explicit 8-deep prefetch pipeline.
__global__ __launch_bounds__(128)
void k_gemm_decode(const float* __restrict__ feat,
                   const float* __restrict__ w_pred,
                   const float* __restrict__ b_pred,
                   float* __restrict__ out)
{
    extern __shared__ float smem_dyn[];
    float* w_s = smem_dyn;                      // CC x OPAD
    float* b_s = smem_dyn + WSMEM_WORDS;        // OO

    const int tid = threadIdx.x;
    const int b   = blockIdx.x >> 2;
    const int n0  = ((blockIdx.x & 3) << 8) | (tid << 1);
    const float2* fp = (const float2*)(feat + (size_t)b * CC * NN) + (n0 >> 1);

    // Stage all weights (padded rows -> ulonglong2-aligned channel pairs)
    for (int i = tid; i < WSMEM_WORDS; i += 128) {
        int c = i / OPAD, o = i - c * OPAD;
        w_s[i] = (o < OO) ? w_pred[o * CC + c] : 0.0f;
    }
    if (tid < OO) b_s[tid] = b_pred[tid];
    __syncthreads();

    u64 accA[13], accB[13];                     // channel pairs {2q,2q+1}, px0/px1
    #pragma unroll
    for (int q = 0; q < 13; q++) { accA[q] = 0ull; accB[q] = 0ull; }

    float2 buf[PF];
    #pragma unroll
    for (int k = 0; k < PF; k++) buf[k] = __ldg(fp + (size_t)k * (NN / 2));

    #pragma unroll 1
    for (int cc = 0; cc < CC - PF; cc += PF) {
        float2 cur[PF];
        #pragma unroll
        for (int k = 0; k < PF; k++) cur[k] = buf[k];
        #pragma unroll
        for (int k = 0; k < PF; k++)
            buf[k] = __ldg(fp + (size_t)(cc + PF + k) * (NN / 2));
        #pragma unroll
        for (int k = 0; k < PF; k++) {
            u64 fA = pack2(cur[k].x);
            u64 fB = pack2(cur[k].y);
            const ulonglong2* wr = (const ulonglong2*)(w_s + (cc + k) * OPAD);
            #pragma unroll
            for (int j = 0; j < 7; j++) {
                ulonglong2 q = wr[j];           // one LDS.128 -> two channel pairs
                FMA2(accA[2*j], fA, q.x);
                FMA2(accB[2*j], fB, q.x);
                if (2*j + 1 < 13) { FMA2(accA[2*j+1], fA, q.y);
                                    FMA2(accB[2*j+1], fB, q.y); }
            }
        }
    }
    #pragma unroll
    for (int k = 0; k < PF; k++) {              // epilogue: last PF channels
        u64 fA = pack2(buf[k].x);
        u64 fB = pack2(buf[k].y);
        const ulonglong2* wr = (const ulonglong2*)(w_s + (CC - PF + k) * OPAD);
        #pragma unroll
        for (int j = 0; j < 7; j++) {
            ulonglong2 q = wr[j];
            FMA2(accA[2*j], fA, q.x);
            FMA2(accB[2*j], fB, q.x);
            if (2*j + 1 < 13) { FMA2(accA[2*j+1], fA, q.y);
                                FMA2(accB[2*j+1], fB, q.y); }
        }
    }

    float acc0[26], acc1[26];
    #pragma unroll
    for (int q = 0; q < 13; q++) {
        unpack2(accA[q], acc0[2*q], acc0[2*q+1]);
        unpack2(accB[q], acc1[2*q], acc1[2*q+1]);
    }
    decode_write(b, n0,     acc0, b_s, out);
    decode_write(b, n0 + 1, acc1, b_s, out);
}

// NMS: one 128-thread block per (image, class) — R8 ballot-matrix core, fed by
// compact records (no indirect gather) with speculative loads issued in parallel
// with the cnt load (one memory round-trip per block instead of three).
// Class offset 2.0 makes cross-class IoU ~0 => per-class greedy == the
// reference's global sorted loop exactly; sub-threshold boxes excluded at gather.
__global__ __launch_bounds__(128)
void k_nms(float* __restrict__ out)
{
    const int b    = blockIdx.x;
    const int c    = blockIdx.y;
    const int idx  = b * NCLS + c;
    const int tid  = threadIdx.x;
    const int warp = tid >> 5;
    const int lane = tid & 31;

    __shared__ int    s_cnt;
    __shared__ u64    tkey[MAXC];
    __shared__ float4 tbox[MAXC];
    __shared__ float4 sbox[MAXC];    // rank-sorted boxes
    __shared__ float  sarea[MAXC];
    __shared__ short  ssn[MAXC];     // rank-sorted pixel index
    __shared__ uint4  rows[MAXC];    // suppression bit-matrix rows

    // Speculative coalesced loads (slot = tid), independent of cnt; slots >= cnt
    // hold stale-but-initialized data and are never consumed.
    u64    k0 = g_ckey[idx * MAXC + tid];
    float4 b0 = g_cbox[idx * MAXC + tid];
    if (tid == 0) { int ct = g_cnt[idx]; g_cnt[idx] = 0; s_cnt = min(ct, MAXC); }
    tkey[tid] = k0;
    tbox[tid] = b0;
    __syncthreads();

    const int cnt = s_cnt;
    if (cnt == 0) return;

    // Rank sort (keys distinct -> permutation), == jnp.argsort(-scores) stability.
    if (tid < cnt) {
        u64 ki = tkey[tid];
        int rank = 0;
        for (int j = 0; j < cnt; j++) rank += (tkey[j] > ki);
        float4 bx = tbox[tid];
        sbox[rank]  = bx;
        sarea[rank] = __fmul_rn(bx.z - bx.x, bx.w - bx.y);
        ssn[rank]   = (short)(NN - 1 - (int)(ki & 0xffffffffu));
    }
    __syncthreads();

    // Suppression matrix: row i, bit j set iff j>i and IoU(i,j)>thresh.
    const int nch = (cnt + 31) >> 5;
    for (int i = warp; i < cnt; i += 4) {
        float4 kb = sbox[i];
        float  ka = sarea[i];
        unsigned w0 = 0, w1 = 0, w2 = 0, w3 = 0;
        for (int ch = 0; ch < nch; ch++) {
            int j = (ch << 5) + lane;
            bool sup = false;
            if (j < cnt && j > i) {
                float4 ob = sbox[j];
                float xx1 = fmaxf(kb.x, ob.x);
                float yy1 = fmaxf(kb.y, ob.y);
                float xx2 = fminf(kb.z, ob.z);
                float yy2 = fminf(kb.w, ob.w);
                float w = fmaxf(EPS_IOU, xx2 - xx1);
                float h = fmaxf(EPS_IOU, yy2 - yy1);
                float inter = __fmul_rn(w, h);
                float iou = inter / (ka + sarea[j] - inter);
                sup = iou > NMS_T;
            }
            unsigned m = __ballot_sync(FULLM, sup);
            if      (ch == 0) w0 = m;
            else if (ch == 1) w1 = m;
            else if (ch == 2) w2 = m;
            else              w3 = m;
        }
        if (lane == 0) rows[i] = make_uint4(w0, w1, w2, w3);
    }
    __syncthreads();

    // Serial walk (thread 0): act mask in registers, rows[k] loads pipeline.
    if (tid == 0) {
        float* keep = out + (size_t)BB * NN * 6 + (size_t)b * NN;
        unsigned a0 = FULLM, a1 = FULLM, a2 = FULLM, a3 = FULLM;
        for (int k = 0; k < cnt; k++) {
            uint4 r = rows[k];
            unsigned aw = (k < 32) ? a0 : (k < 64) ? a1 : (k < 96) ? a2 : a3;
            if ((aw >> (k & 31)) & 1u) {
                keep[ssn[k]] = 1.0f;
                a0 &= ~r.x; a1 &= ~r.y; a2 &= ~r.z; a3 &= ~r.w;
            }
        }
    }
}

extern "C" void kernel_launch(void* const* d_in, const int* in_sizes, int n_in,
                              void* d_out, int out_size)
{
    const float* feat   = (const float*)d_in[0];
    const float* w_pred = (const float*)d_in[1];
    const float* b_pred = (const float*)d_in[2];
    float* out = (float*)d_out;

    static int smem_set = 0;
    if (!smem_set) {
        cudaFuncSetAttribute(k_gemm_decode,
                             cudaFuncAttributeMaxDynamicSharedMemorySize, SMEM_BYTES);
        smem_set = 1;
    }

    k_gemm_decode<<<256, 128, SMEM_BYTES>>>(feat, w_pred, b_pred, out);
    k_nms<<<dim3(BB, NCLS), 128>>>(out);
}